// round 1
// baseline (speedup 1.0000x reference)
#include <cuda_runtime.h>
#include <cstddef>

#define Bn 8
#define Tn 2048
#define En 1024
#define Hn 64

// Scratch for projected Q, K, V (no cudaMalloc allowed)
__device__ float g_q[Bn * Tn * Hn];
__device__ float g_k[Bn * Tn * Hn];
__device__ float g_v[Bn * Tn * Hn];

// ---------------------------------------------------------------------------
// Fused QKV projection.
// grid: (B*T/32) blocks, 256 threads.
// Each block computes rows [m0, m0+32) x all 64 cols of Q, K, V.
// x tile loaded to smem once, reused for all three weight matrices.
// ---------------------------------------------------------------------------
__global__ __launch_bounds__(256) void qkv_kernel(
    const float* __restrict__ x,
    const float* __restrict__ Wq,
    const float* __restrict__ Wk,
    const float* __restrict__ Wv)
{
    __shared__ float xs[32][32];     // 32 rows x 32 e-chunk
    __shared__ float wqs[32][64];
    __shared__ float wks[32][64];
    __shared__ float wvs[32][64];

    const int m0  = blockIdx.x * 32;
    const int tid = threadIdx.x;
    const int h   = tid & 63;        // output column
    const int g   = tid >> 6;        // row group 0..3 -> rows g*8 .. g*8+7

    float accq[8], acck[8], accv[8];
#pragma unroll
    for (int r = 0; r < 8; r++) { accq[r] = 0.f; acck[r] = 0.f; accv[r] = 0.f; }

    for (int e0 = 0; e0 < En; e0 += 32) {
        __syncthreads();
        // load x tile: 32 rows x 32 e (coalesced 128B per row-warp)
        for (int idx = tid; idx < 32 * 32; idx += 256) {
            int r = idx >> 5, e = idx & 31;
            xs[r][e] = x[(size_t)(m0 + r) * En + e0 + e];
        }
        // load W chunks: each is 32x64 contiguous floats
        for (int idx = tid; idx < 32 * 64; idx += 256) {
            wqs[idx >> 6][idx & 63] = Wq[(size_t)e0 * Hn + idx];
            wks[idx >> 6][idx & 63] = Wk[(size_t)e0 * Hn + idx];
            wvs[idx >> 6][idx & 63] = Wv[(size_t)e0 * Hn + idx];
        }
        __syncthreads();

#pragma unroll 4
        for (int e = 0; e < 32; e++) {
            float wq = wqs[e][h];
            float wk = wks[e][h];
            float wv = wvs[e][h];
#pragma unroll
            for (int rr = 0; rr < 8; rr++) {
                float xv = xs[g * 8 + rr][e];   // broadcast across h-lanes
                accq[rr] += xv * wq;
                acck[rr] += xv * wk;
                accv[rr] += xv * wv;
            }
        }
    }

#pragma unroll
    for (int rr = 0; rr < 8; rr++) {
        size_t o = (size_t)(m0 + g * 8 + rr) * Hn + h;
        g_q[o] = accq[rr];
        g_k[o] = acck[rr];
        g_v[o] = accv[rr];
    }
}

// ---------------------------------------------------------------------------
// Flash attention (causal), fp32.
// grid: (T/64, B), 256 threads per block.
// Each block: 64 query rows, streams 64-key tiles up to the diagonal.
// Online softmax; O accumulators in registers (16 per thread).
// Dynamic smem layout:
//   Qs [64][64]   (broadcast reads, no pad needed)
//   Kt [64][65]   K transposed: Kt[e][n]
//   Vs [64][65]   Vs[n][h]
//   Ss [64][65]   scores / probabilities
// ---------------------------------------------------------------------------
#define QS(r, e) smem[(r) * 64 + (e)]
#define KT(e, n) smem[4096 + (e) * 65 + (n)]
#define VS(n, h) smem[4096 + 4160 + (n) * 65 + (h)]
#define SS(r, n) smem[4096 + 8320 + (r) * 65 + (n)]
#define ATTN_SMEM_FLOATS (4096 + 3 * 4160)

__global__ __launch_bounds__(256) void attn_kernel(float* __restrict__ out)
{
    extern __shared__ float smem[];
    __shared__ float rowm[64], rowl[64], alphas[64];

    const int b   = blockIdx.y;
    const int i0  = blockIdx.x * 64;
    const int tid = threadIdx.x;
    const int c   = tid & 63;        // column: key index n, or head dim h
    const int rg  = tid >> 6;        // rows rg, rg+4, ..., rg+60

    const float* q = g_q + (size_t)b * Tn * Hn;
    const float* k = g_k + (size_t)b * Tn * Hn;
    const float* v = g_v + (size_t)b * Tn * Hn;

    // load Q tile
    for (int idx = tid; idx < 64 * 64; idx += 256) {
        int r = idx >> 6, e = idx & 63;
        QS(r, e) = q[(size_t)(i0 + r) * Hn + e];
    }
    if (tid < 64) { rowm[tid] = -1e30f; rowl[tid] = 0.f; }

    float O[16];
#pragma unroll
    for (int i = 0; i < 16; i++) O[i] = 0.f;

    for (int j0 = 0; j0 <= i0; j0 += 64) {
        __syncthreads();   // protect Kt/Vs/Ss reuse from previous iteration
        // load K (transposed) and V tiles
        for (int idx = tid; idx < 64 * 64; idx += 256) {
            int n = idx >> 6, e = idx & 63;
            float kval = k[(size_t)(j0 + n) * Hn + e];
            float vval = v[(size_t)(j0 + n) * Hn + e];
            KT(e, n) = kval;
            VS(n, e) = vval;
        }
        __syncthreads();

        // S = Q K^T
        float s[16];
#pragma unroll
        for (int i = 0; i < 16; i++) s[i] = 0.f;
        for (int e = 0; e < 64; e++) {
            float kv = KT(e, c);
#pragma unroll
            for (int i = 0; i < 16; i++)
                s[i] += QS(rg + 4 * i, e) * kv;   // Q broadcast across lanes
        }

        // scale + causal mask + store to smem
#pragma unroll
        for (int i = 0; i < 16; i++) {
            int r = rg + 4 * i;
            float val = s[i] * 0.125f;            // 1/sqrt(64)
            if (j0 + c > i0 + r) val = -1e30f;    // only fires on diagonal tile
            SS(r, c) = val;
        }
        __syncthreads();

        // online softmax: one thread per row
        if (tid < 64) {
            int r = tid;
            float m_old = rowm[r];
            float m_new = m_old;
            for (int n = 0; n < 64; n++) m_new = fmaxf(m_new, SS(r, n));
            float al  = __expf(m_old - m_new);
            float sum = 0.f;
            for (int n = 0; n < 64; n++) {
                float p = __expf(SS(r, n) - m_new);
                SS(r, n) = p;
                sum += p;
            }
            rowl[r]   = rowl[r] * al + sum;
            rowm[r]   = m_new;
            alphas[r] = al;
        }
        __syncthreads();

        // O = O * alpha + P V
#pragma unroll
        for (int i = 0; i < 16; i++) O[i] *= alphas[rg + 4 * i];
        for (int n = 0; n < 64; n++) {
            float vv = VS(n, c);
#pragma unroll
            for (int i = 0; i < 16; i++)
                O[i] += SS(rg + 4 * i, n) * vv;   // P broadcast across lanes
        }
    }

    // final normalize + write
#pragma unroll
    for (int i = 0; i < 16; i++) {
        int r = rg + 4 * i;
        out[((size_t)b * Tn + i0 + r) * Hn + c] = O[i] / rowl[r];
    }
}

extern "C" void kernel_launch(void* const* d_in, const int* in_sizes, int n_in,
                              void* d_out, int out_size)
{
    const float* x  = (const float*)d_in[0];
    const float* Wq = (const float*)d_in[1];
    const float* Wk = (const float*)d_in[2];
    const float* Wv = (const float*)d_in[3];
    float* out = (float*)d_out;
    (void)in_sizes; (void)n_in; (void)out_size;

    // QKV projection: 512 blocks x 256 threads
    qkv_kernel<<<(Bn * Tn) / 32, 256>>>(x, Wq, Wk, Wv);

    // Flash attention: (32, 8) blocks x 256 threads, ~65KB dynamic smem
    const int attn_smem = ATTN_SMEM_FLOATS * (int)sizeof(float);
    cudaFuncSetAttribute(attn_kernel,
                         cudaFuncAttributeMaxDynamicSharedMemorySize, attn_smem);
    dim3 grid(Tn / 64, Bn);
    attn_kernel<<<grid, 256, attn_smem>>>(out);
}

// round 2
// speedup vs baseline: 1.3304x; 1.3304x over previous
#include <cuda_runtime.h>
#include <cstddef>

#define Bn 8
#define Tn 2048
#define En 1024
#define Hn 64

// Scratch for projected Q, K, V (no cudaMalloc allowed)
__device__ float g_q[Bn * Tn * Hn];
__device__ float g_k[Bn * Tn * Hn];
__device__ float g_v[Bn * Tn * Hn];

// ---------------------------------------------------------------------------
// Fused QKV projection.
// grid: (B*T/32) blocks, 256 threads.
// Each block: rows [m0, m0+32) x 64 cols of Q, K, V.
// W stored transposed in smem so inner loop uses float4 loads.
// ---------------------------------------------------------------------------
__global__ __launch_bounds__(256) void qkv_kernel(
    const float* __restrict__ x,
    const float* __restrict__ Wq,
    const float* __restrict__ Wk,
    const float* __restrict__ Wv)
{
    __shared__ float xs[32][36];      // [row][e] pad->36 for bank spread, f4-aligned
    __shared__ float wqs[64][36];     // [h][e] transposed
    __shared__ float wks[64][36];
    __shared__ float wvs[64][36];

    const int m0  = blockIdx.x * 32;
    const int tid = threadIdx.x;
    const int h   = tid & 63;         // output column
    const int g   = tid >> 6;         // row group: rows g*8 .. g*8+7

    float accq[8], acck[8], accv[8];
#pragma unroll
    for (int r = 0; r < 8; r++) { accq[r] = 0.f; acck[r] = 0.f; accv[r] = 0.f; }

    for (int e0 = 0; e0 < En; e0 += 32) {
        __syncthreads();
        // x tile: 32 rows x 32 e, float4 loads+stores
        for (int idx = tid; idx < 32 * 8; idx += 256) {
            int r = idx >> 3, e4 = (idx & 7) * 4;
            float4 xv = *(const float4*)&x[(size_t)(m0 + r) * En + e0 + e4];
            *(float4*)&xs[r][e4] = xv;
        }
        // W chunks: 32e x 64h each, coalesced load, transposed store
        for (int idx = tid; idx < 32 * 64; idx += 256) {
            int e = idx >> 6, hh = idx & 63;
            wqs[hh][e] = Wq[(size_t)(e0 + e) * Hn + hh];
            wks[hh][e] = Wk[(size_t)(e0 + e) * Hn + hh];
            wvs[hh][e] = Wv[(size_t)(e0 + e) * Hn + hh];
        }
        __syncthreads();

#pragma unroll
        for (int e = 0; e < 32; e += 4) {
            float4 wq4 = *(const float4*)&wqs[h][e];
            float4 wk4 = *(const float4*)&wks[h][e];
            float4 wv4 = *(const float4*)&wvs[h][e];
#pragma unroll
            for (int rr = 0; rr < 8; rr++) {
                float4 xv = *(const float4*)&xs[g * 8 + rr][e];
                accq[rr] += xv.x * wq4.x + xv.y * wq4.y + xv.z * wq4.z + xv.w * wq4.w;
                acck[rr] += xv.x * wk4.x + xv.y * wk4.y + xv.z * wk4.z + xv.w * wk4.w;
                accv[rr] += xv.x * wv4.x + xv.y * wv4.y + xv.z * wv4.z + xv.w * wv4.w;
            }
        }
    }

#pragma unroll
    for (int rr = 0; rr < 8; rr++) {
        size_t o = (size_t)(m0 + g * 8 + rr) * Hn + h;
        g_q[o] = accq[rr];
        g_k[o] = acck[rr];
        g_v[o] = accv[rr];
    }
}

// ---------------------------------------------------------------------------
// Flash attention (causal), fp32, fully parallel online softmax.
// grid: (T/64, B) [reversed for triangular load balance], 256 threads.
//
// Layout A (QK + softmax): thread = (rgrp = tid>>4, cg = tid&15)
//   owns rows r0=rgrp*4 .. +3, cols c0=cg*4 .. +3 of the 64x64 S tile.
//   Row reductions via shfl_xor within 16-lane groups; exps in registers.
//   P written TRANSPOSED to smem: PT[n][r].
// Layout B (PV): thread = (rg = tid>>6, c = tid&63) owns rows rg*16..+15,
//   column c. PT reads are float4 broadcasts.
//
// Dyn smem (floats): QS[64][68] | KT[64][68] | VS[64][64] | PT[64][68]
// ---------------------------------------------------------------------------
#define QS_OFF 0
#define KT_OFF 4352
#define VS_OFF 8704
#define PT_OFF 12800
#define ATTN_SMEM_FLOATS 17152

#define QS(r, e) smem[QS_OFF + (r) * 68 + (e)]
#define KT(e, n) smem[KT_OFF + (e) * 68 + (n)]
#define VS(n, h) smem[VS_OFF + (n) * 64 + (h)]
#define PT(n, r) smem[PT_OFF + (n) * 68 + (r)]

__global__ __launch_bounds__(256) void attn_kernel(float* __restrict__ out)
{
    extern __shared__ float smem[];
    __shared__ float rowm[64], rowl[64], alphas[64];

    const int b   = blockIdx.y;
    const int i0  = (gridDim.x - 1 - blockIdx.x) * 64;   // heavy blocks first
    const int tid = threadIdx.x;

    // layout A coords
    const int rgrp = tid >> 4;
    const int r0   = rgrp * 4;
    const int cg   = tid & 15;
    const int c0   = cg * 4;
    // layout B coords
    const int c    = tid & 63;
    const int r0b  = (tid >> 6) * 16;

    const float* q = g_q + (size_t)b * Tn * Hn;
    const float* k = g_k + (size_t)b * Tn * Hn;
    const float* v = g_v + (size_t)b * Tn * Hn;

    // prologue: Q tile (float4), row state init
    for (int idx = tid; idx < 64 * 16; idx += 256) {
        int r = idx >> 4, e4 = (idx & 15) * 4;
        float4 qv = *(const float4*)&q[(size_t)(i0 + r) * Hn + e4];
        *(float4*)&QS(r, e4) = qv;
    }
    if (tid < 64) { rowm[tid] = -1e30f; rowl[tid] = 0.f; }

    float4 O[4];
#pragma unroll
    for (int i = 0; i < 4; i++) O[i] = make_float4(0.f, 0.f, 0.f, 0.f);

    for (int j0 = 0; j0 <= i0; j0 += 64) {
        const bool diag = (j0 == i0);
        __syncthreads();    // protect KT/VS/PT/state reuse

        // ---- load K (transposed) and V tiles ----
        for (int idx = tid; idx < 64 * 16; idx += 256) {
            int n = idx >> 4, e4 = (idx & 15) * 4;
            float4 kv4 = *(const float4*)&k[(size_t)(j0 + n) * Hn + e4];
            float4 vv4 = *(const float4*)&v[(size_t)(j0 + n) * Hn + e4];
            *(float4*)&VS(n, e4) = vv4;
            KT(e4 + 0, n) = kv4.x;
            KT(e4 + 1, n) = kv4.y;
            KT(e4 + 2, n) = kv4.z;
            KT(e4 + 3, n) = kv4.w;
        }
        __syncthreads();

        // ---- S = Q K^T : 4 rows x 4 cols per thread ----
        float s[4][4];
#pragma unroll
        for (int i = 0; i < 4; i++)
#pragma unroll
            for (int j = 0; j < 4; j++) s[i][j] = 0.f;

#pragma unroll
        for (int e = 0; e < 64; e += 4) {
            float4 q0 = *(const float4*)&QS(r0 + 0, e);
            float4 q1 = *(const float4*)&QS(r0 + 1, e);
            float4 q2 = *(const float4*)&QS(r0 + 2, e);
            float4 q3 = *(const float4*)&QS(r0 + 3, e);
#pragma unroll
            for (int se = 0; se < 4; se++) {
                float4 kv = *(const float4*)&KT(e + se, c0);
                float qe0 = (se == 0) ? q0.x : (se == 1) ? q0.y : (se == 2) ? q0.z : q0.w;
                float qe1 = (se == 0) ? q1.x : (se == 1) ? q1.y : (se == 2) ? q1.z : q1.w;
                float qe2 = (se == 0) ? q2.x : (se == 1) ? q2.y : (se == 2) ? q2.z : q2.w;
                float qe3 = (se == 0) ? q3.x : (se == 1) ? q3.y : (se == 2) ? q3.z : q3.w;
                s[0][0] += qe0 * kv.x; s[0][1] += qe0 * kv.y; s[0][2] += qe0 * kv.z; s[0][3] += qe0 * kv.w;
                s[1][0] += qe1 * kv.x; s[1][1] += qe1 * kv.y; s[1][2] += qe1 * kv.z; s[1][3] += qe1 * kv.w;
                s[2][0] += qe2 * kv.x; s[2][1] += qe2 * kv.y; s[2][2] += qe2 * kv.z; s[2][3] += qe2 * kv.w;
                s[3][0] += qe3 * kv.x; s[3][1] += qe3 * kv.y; s[3][2] += qe3 * kv.z; s[3][3] += qe3 * kv.w;
            }
        }

        // ---- scale, mask, parallel online softmax ----
#pragma unroll
        for (int i = 0; i < 4; i++) {
#pragma unroll
            for (int j = 0; j < 4; j++) {
                float val = s[i][j] * 0.125f;
                if (diag && (c0 + j > r0 + i)) val = -1e30f;
                s[i][j] = val;
            }
        }

        float al4[4], linc[4];
#pragma unroll
        for (int i = 0; i < 4; i++) {
            float m = fmaxf(fmaxf(s[i][0], s[i][1]), fmaxf(s[i][2], s[i][3]));
#pragma unroll
            for (int msk = 1; msk < 16; msk <<= 1)
                m = fmaxf(m, __shfl_xor_sync(0xFFFFFFFFu, m, msk));
            float m_old = rowm[r0 + i];
            float m_new = fmaxf(m_old, m);
            float sum = 0.f;
#pragma unroll
            for (int j = 0; j < 4; j++) {
                float p = __expf(s[i][j] - m_new);
                s[i][j] = p;
                sum += p;
            }
#pragma unroll
            for (int msk = 1; msk < 16; msk <<= 1)
                sum += __shfl_xor_sync(0xFFFFFFFFu, sum, msk);
            al4[i]  = __expf(m_old - m_new);
            linc[i] = sum;
            if (cg == 0) rowm[r0 + i] = m_new;
        }
        if (cg == 0) {
#pragma unroll
            for (int i = 0; i < 4; i++) {
                rowl[r0 + i]   = rowl[r0 + i] * al4[i] + linc[i];
                alphas[r0 + i] = al4[i];
            }
        }

        // P transposed to smem: PT[n][r], float4 over rows
#pragma unroll
        for (int j = 0; j < 4; j++) {
            float4 pj = make_float4(s[0][j], s[1][j], s[2][j], s[3][j]);
            *(float4*)&PT(c0 + j, r0) = pj;
        }
        __syncthreads();

        // ---- O = O*alpha + P V (layout B) ----
#pragma unroll
        for (int i = 0; i < 4; i++) {
            float a0 = alphas[r0b + 4 * i + 0];
            float a1 = alphas[r0b + 4 * i + 1];
            float a2 = alphas[r0b + 4 * i + 2];
            float a3 = alphas[r0b + 4 * i + 3];
            O[i].x *= a0; O[i].y *= a1; O[i].z *= a2; O[i].w *= a3;
        }
#pragma unroll 4
        for (int n = 0; n < 64; n++) {
            float vv = VS(n, c);
            float4 p0 = *(const float4*)&PT(n, r0b + 0);
            float4 p1 = *(const float4*)&PT(n, r0b + 4);
            float4 p2 = *(const float4*)&PT(n, r0b + 8);
            float4 p3 = *(const float4*)&PT(n, r0b + 12);
            O[0].x += p0.x * vv; O[0].y += p0.y * vv; O[0].z += p0.z * vv; O[0].w += p0.w * vv;
            O[1].x += p1.x * vv; O[1].y += p1.y * vv; O[1].z += p1.z * vv; O[1].w += p1.w * vv;
            O[2].x += p2.x * vv; O[2].y += p2.y * vv; O[2].z += p2.z * vv; O[2].w += p2.w * vv;
            O[3].x += p3.x * vv; O[3].y += p3.y * vv; O[3].z += p3.z * vv; O[3].w += p3.w * vv;
        }
    }

    // epilogue: normalize + write (rowl written before last pre-PV sync)
#pragma unroll
    for (int i = 0; i < 4; i++) {
        float* op = (float*)&O[i];
#pragma unroll
        for (int u = 0; u < 4; u++) {
            int r = r0b + 4 * i + u;
            out[((size_t)b * Tn + i0 + r) * Hn + c] = op[u] / rowl[r];
        }
    }
}

extern "C" void kernel_launch(void* const* d_in, const int* in_sizes, int n_in,
                              void* d_out, int out_size)
{
    const float* x  = (const float*)d_in[0];
    const float* Wq = (const float*)d_in[1];
    const float* Wk = (const float*)d_in[2];
    const float* Wv = (const float*)d_in[3];
    float* out = (float*)d_out;
    (void)in_sizes; (void)n_in; (void)out_size;

    qkv_kernel<<<(Bn * Tn) / 32, 256>>>(x, Wq, Wk, Wv);

    const int attn_smem = ATTN_SMEM_FLOATS * (int)sizeof(float);
    cudaFuncSetAttribute(attn_kernel,
                         cudaFuncAttributeMaxDynamicSharedMemorySize, attn_smem);
    dim3 grid(Tn / 64, Bn);
    attn_kernel<<<grid, 256, attn_smem>>>(out);
}

// round 5
// speedup vs baseline: 2.3685x; 1.7803x over previous
#include <cuda_runtime.h>
#include <cuda_fp16.h>
#include <mma.h>
#include <cstddef>

using namespace nvcuda;

#define Bn 8
#define Tn 2048
#define En 1024
#define Hn 64

// Scratch (no cudaMalloc allowed)
__device__ float  g_q[Bn * Tn * Hn];
__device__ float  g_k[Bn * Tn * Hn];
__device__ float  g_v[Bn * Tn * Hn];
__device__ __half g_wt[3 * Hn * En];   // [mat][h][e] fp16, pitch En

// ---------------------------------------------------------------------------
// W transpose pre-kernel: W[e][h] fp32 -> g_wt[mat][h][e] fp16.
// ---------------------------------------------------------------------------
__global__ __launch_bounds__(256) void wtrans_kernel(
    const float* __restrict__ Wq,
    const float* __restrict__ Wk,
    const float* __restrict__ Wv)
{
    __shared__ float t[64][65];
    const int mat = blockIdx.y;
    const int e0  = blockIdx.x * 64;
    const float* W = (mat == 0) ? Wq : (mat == 1) ? Wk : Wv;

    for (int idx = threadIdx.x; idx < 64 * 64; idx += 256) {
        int e = idx >> 6, h = idx & 63;
        t[e][h] = W[(size_t)(e0 + e) * Hn + h];
    }
    __syncthreads();
    for (int idx = threadIdx.x; idx < 64 * 64; idx += 256) {
        int h = idx >> 6, e = idx & 63;
        g_wt[(size_t)(mat * Hn + h) * En + e0 + e] = __float2half_rn(t[e][h]);
    }
}

// ---------------------------------------------------------------------------
// QKV projection via WMMA (m16n16k16, f16 -> f32).
// grid: B*T/64 = 256 blocks, 256 threads (8 warps).
// Warp w: row-tile rt = w&3 (16 rows), col-tiles {(w>>2)*2, +1}, all 3 mats.
// smem pitch 72 halfs (144B) -> 16B-aligned fragment bases, bank-spread.
// ---------------------------------------------------------------------------
__global__ __launch_bounds__(256) void qkv_wmma_kernel(
    const float* __restrict__ x)
{
    __shared__ __align__(32) __half xs[64][72];        // [row][k]
    __shared__ __align__(32) __half ws[3][64][72];     // [mat][n=h][k]

    const int tid  = threadIdx.x;
    const int warp = tid >> 5;
    const int m0   = blockIdx.x * 64;
    const int rt   = warp & 3;
    const int ctb  = (warp >> 2) * 2;

    wmma::fragment<wmma::accumulator, 16, 16, 16, float> acc[3][2];
#pragma unroll
    for (int m = 0; m < 3; m++)
#pragma unroll
        for (int i = 0; i < 2; i++) wmma::fill_fragment(acc[m][i], 0.f);

    for (int e0 = 0; e0 < En; e0 += 64) {
        __syncthreads();
        // x tile: 64 rows x 64 k, fp32 -> fp16
        for (int idx = tid; idx < 64 * 16; idx += 256) {
            int r = idx >> 4, e4 = (idx & 15) * 4;
            float4 v = *(const float4*)&x[(size_t)(m0 + r) * En + e0 + e4];
            *(__half2*)&xs[r][e4]     = __floats2half2_rn(v.x, v.y);
            *(__half2*)&xs[r][e4 + 2] = __floats2half2_rn(v.z, v.w);
        }
        // W chunks: fp16 pre-transposed in gmem, straight copy.
        // 8 halfs = 16 bytes per iteration -> uint4 (NOT uint2: that was the
        // NaN bug — it copied only 4 halfs, leaving half of ws uninitialized).
        for (int idx = tid; idx < 3 * 64 * 8; idx += 256) {
            int mat = idx >> 9;
            int rem = idx & 511;
            int h   = rem >> 3;
            int c8  = (rem & 7) * 8;
            *(uint4*)&ws[mat][h][c8] =
                *(const uint4*)&g_wt[(size_t)(mat * Hn + h) * En + e0 + c8];
        }
        __syncthreads();

#pragma unroll
        for (int ks = 0; ks < 4; ks++) {
            wmma::fragment<wmma::matrix_a, 16, 16, 16, __half, wmma::row_major> a;
            wmma::load_matrix_sync(a, &xs[rt * 16][ks * 16], 72);
#pragma unroll
            for (int mat = 0; mat < 3; mat++) {
#pragma unroll
                for (int i = 0; i < 2; i++) {
                    wmma::fragment<wmma::matrix_b, 16, 16, 16, __half, wmma::col_major> b;
                    wmma::load_matrix_sync(b, &ws[mat][(ctb + i) * 16][ks * 16], 72);
                    wmma::mma_sync(acc[mat][i], a, b, acc[mat][i]);
                }
            }
        }
    }

#pragma unroll
    for (int mat = 0; mat < 3; mat++) {
        float* dst = (mat == 0) ? g_q : (mat == 1) ? g_k : g_v;
#pragma unroll
        for (int i = 0; i < 2; i++) {
            wmma::store_matrix_sync(
                &dst[(size_t)(m0 + rt * 16) * Hn + (ctb + i) * 16],
                acc[mat][i], Hn, wmma::mem_row_major);
        }
    }
}

// ---------------------------------------------------------------------------
// Flash attention (causal): QK^T on WMMA (f16 in, f32 out to smem SS),
// softmax + PV in fp32 (proven R2 code paths).
// grid: (T/64, B) reversed, 256 threads (8 warps).
//
// Dyn smem (bytes):
//   QH  half[64][72]   @ 0       (9216)
//   KH  half[64][72]   @ 9216    (9216)
//   VS  float[64][64]  @ 18432   (16384)
//   SS  float[64][68]  @ 34816   (17408)
//   PT  float[64][68]  @ 52224   (17408)
//   total 69632
// ---------------------------------------------------------------------------
#define ATTN_SMEM_BYTES 69632

__global__ __launch_bounds__(256) void attn_kernel(float* __restrict__ out)
{
    extern __shared__ __align__(32) char dyn[];
    __half (*QH)[72] = (__half(*)[72])(dyn);
    __half (*KH)[72] = (__half(*)[72])(dyn + 9216);
    float  (*VSp)[64] = (float(*)[64])(dyn + 18432);
    float  (*SSp)[68] = (float(*)[68])(dyn + 34816);
    float  (*PTp)[68] = (float(*)[68])(dyn + 52224);
    __shared__ float rowm[64], rowl[64], alphas[64];

    const int b   = blockIdx.y;
    const int i0  = (gridDim.x - 1 - blockIdx.x) * 64;   // heavy blocks first
    const int tid = threadIdx.x;
    const int warp = tid >> 5;

    // wmma tile coords: warp -> row-tile rt, col-tiles {ctb, ctb+1}
    const int rt  = warp & 3;
    const int ctb = (warp >> 2) * 2;
    // softmax layout coords
    const int r0 = (tid >> 4) * 4;
    const int cg = tid & 15;
    const int c0 = cg * 4;
    // PV layout coords
    const int c   = tid & 63;
    const int r0b = (tid >> 6) * 16;

    const float* q = g_q + (size_t)b * Tn * Hn;
    const float* k = g_k + (size_t)b * Tn * Hn;
    const float* v = g_v + (size_t)b * Tn * Hn;

    // prologue: Q tile -> fp16 smem
    for (int idx = tid; idx < 64 * 16; idx += 256) {
        int r = idx >> 4, e4 = (idx & 15) * 4;
        float4 qv = *(const float4*)&q[(size_t)(i0 + r) * Hn + e4];
        *(__half2*)&QH[r][e4]     = __floats2half2_rn(qv.x, qv.y);
        *(__half2*)&QH[r][e4 + 2] = __floats2half2_rn(qv.z, qv.w);
    }
    if (tid < 64) { rowm[tid] = -1e30f; rowl[tid] = 0.f; }

    float4 O[4];
#pragma unroll
    for (int i = 0; i < 4; i++) O[i] = make_float4(0.f, 0.f, 0.f, 0.f);

    for (int j0 = 0; j0 <= i0; j0 += 64) {
        const bool diag = (j0 == i0);
        __syncthreads();    // protect KH/VS/SS/PT reuse

        // ---- load K (fp16, natural [n][e]) and V (fp32) tiles ----
        for (int idx = tid; idx < 64 * 16; idx += 256) {
            int n = idx >> 4, e4 = (idx & 15) * 4;
            float4 kv4 = *(const float4*)&k[(size_t)(j0 + n) * Hn + e4];
            float4 vv4 = *(const float4*)&v[(size_t)(j0 + n) * Hn + e4];
            *(float4*)&VSp[n][e4] = vv4;
            *(__half2*)&KH[n][e4]     = __floats2half2_rn(kv4.x, kv4.y);
            *(__half2*)&KH[n][e4 + 2] = __floats2half2_rn(kv4.z, kv4.w);
        }
        __syncthreads();

        // ---- S = Q K^T via WMMA: each warp 2 tiles of the 4x4 tile grid ----
        {
            wmma::fragment<wmma::accumulator, 16, 16, 16, float> sacc[2];
            wmma::fill_fragment(sacc[0], 0.f);
            wmma::fill_fragment(sacc[1], 0.f);
#pragma unroll
            for (int ks = 0; ks < 4; ks++) {
                wmma::fragment<wmma::matrix_a, 16, 16, 16, __half, wmma::row_major> af;
                wmma::load_matrix_sync(af, &QH[rt * 16][ks * 16], 72);
#pragma unroll
                for (int i = 0; i < 2; i++) {
                    wmma::fragment<wmma::matrix_b, 16, 16, 16, __half, wmma::col_major> bf;
                    wmma::load_matrix_sync(bf, &KH[(ctb + i) * 16][ks * 16], 72);
                    wmma::mma_sync(sacc[i], af, bf, sacc[i]);
                }
            }
#pragma unroll
            for (int i = 0; i < 2; i++)
                wmma::store_matrix_sync(&SSp[rt * 16][(ctb + i) * 16], sacc[i],
                                        68, wmma::mem_row_major);
        }
        __syncthreads();

        // ---- scale, mask, parallel online softmax (reads SS) ----
        float s[4][4];
#pragma unroll
        for (int i = 0; i < 4; i++) {
#pragma unroll
            for (int j = 0; j < 4; j++) {
                float val = SSp[r0 + i][c0 + j] * 0.125f;
                if (diag && (c0 + j > r0 + i)) val = -1e30f;
                s[i][j] = val;
            }
        }

        float al4[4], linc[4];
#pragma unroll
        for (int i = 0; i < 4; i++) {
            float m = fmaxf(fmaxf(s[i][0], s[i][1]), fmaxf(s[i][2], s[i][3]));
#pragma unroll
            for (int msk = 1; msk < 16; msk <<= 1)
                m = fmaxf(m, __shfl_xor_sync(0xFFFFFFFFu, m, msk));
            float m_old = rowm[r0 + i];
            float m_new = fmaxf(m_old, m);
            float sum = 0.f;
#pragma unroll
            for (int j = 0; j < 4; j++) {
                float p = __expf(s[i][j] - m_new);
                s[i][j] = p;
                sum += p;
            }
#pragma unroll
            for (int msk = 1; msk < 16; msk <<= 1)
                sum += __shfl_xor_sync(0xFFFFFFFFu, sum, msk);
            al4[i]  = __expf(m_old - m_new);
            linc[i] = sum;
            if (cg == 0) rowm[r0 + i] = m_new;
        }
        if (cg == 0) {
#pragma unroll
            for (int i = 0; i < 4; i++) {
                rowl[r0 + i]   = rowl[r0 + i] * al4[i] + linc[i];
                alphas[r0 + i] = al4[i];
            }
        }

        // P transposed to smem: PT[n][r]
#pragma unroll
        for (int j = 0; j < 4; j++) {
            float4 pj = make_float4(s[0][j], s[1][j], s[2][j], s[3][j]);
            *(float4*)&PTp[c0 + j][r0] = pj;
        }
        __syncthreads();

        // ---- O = O*alpha + P V (fp32) ----
#pragma unroll
        for (int i = 0; i < 4; i++) {
            float a0 = alphas[r0b + 4 * i + 0];
            float a1 = alphas[r0b + 4 * i + 1];
            float a2 = alphas[r0b + 4 * i + 2];
            float a3 = alphas[r0b + 4 * i + 3];
            O[i].x *= a0; O[i].y *= a1; O[i].z *= a2; O[i].w *= a3;
        }
#pragma unroll 4
        for (int n = 0; n < 64; n++) {
            float vv = VSp[n][c];
            float4 p0 = *(const float4*)&PTp[n][r0b + 0];
            float4 p1 = *(const float4*)&PTp[n][r0b + 4];
            float4 p2 = *(const float4*)&PTp[n][r0b + 8];
            float4 p3 = *(const float4*)&PTp[n][r0b + 12];
            O[0].x += p0.x * vv; O[0].y += p0.y * vv; O[0].z += p0.z * vv; O[0].w += p0.w * vv;
            O[1].x += p1.x * vv; O[1].y += p1.y * vv; O[1].z += p1.z * vv; O[1].w += p1.w * vv;
            O[2].x += p2.x * vv; O[2].y += p2.y * vv; O[2].z += p2.z * vv; O[2].w += p2.w * vv;
            O[3].x += p3.x * vv; O[3].y += p3.y * vv; O[3].z += p3.z * vv; O[3].w += p3.w * vv;
        }
    }

    // epilogue: normalize + write
#pragma unroll
    for (int i = 0; i < 4; i++) {
        float* op = (float*)&O[i];
#pragma unroll
        for (int u = 0; u < 4; u++) {
            int r = r0b + 4 * i + u;
            out[((size_t)b * Tn + i0 + r) * Hn + c] = op[u] / rowl[r];
        }
    }
}

extern "C" void kernel_launch(void* const* d_in, const int* in_sizes, int n_in,
                              void* d_out, int out_size)
{
    const float* x  = (const float*)d_in[0];
    const float* Wq = (const float*)d_in[1];
    const float* Wk = (const float*)d_in[2];
    const float* Wv = (const float*)d_in[3];
    float* out = (float*)d_out;
    (void)in_sizes; (void)n_in; (void)out_size;

    dim3 wgrid(En / 64, 3);
    wtrans_kernel<<<wgrid, 256>>>(Wq, Wk, Wv);

    qkv_wmma_kernel<<<(Bn * Tn) / 64, 256>>>(x);

    cudaFuncSetAttribute(attn_kernel,
                         cudaFuncAttributeMaxDynamicSharedMemorySize,
                         ATTN_SMEM_BYTES);
    dim3 grid(Tn / 64, Bn);
    attn_kernel<<<grid, 256, ATTN_SMEM_BYTES>>>(out);
}

// round 6
// speedup vs baseline: 5.7016x; 2.4073x over previous
#include <cuda_runtime.h>
#include <cuda_fp16.h>
#include <mma.h>
#include <cstddef>

using namespace nvcuda;

#define Bn 8
#define Tn 2048
#define En 1024
#define Hn 64

// Scratch (no cudaMalloc allowed)
__device__ float  g_q [Bn * Tn * Hn];           // [b][t][h]
__device__ float  g_k [Bn * Tn * Hn];           // [b][t][h]
__device__ float  g_vt[Bn * Hn * Tn];           // [b][h][t]  (transposed V)
__device__ __half g_wt[3 * Hn * En];            // [mat][h][e] fp16

// ---------------------------------------------------------------------------
// W transpose pre-kernel: W[e][h] fp32 -> g_wt[mat][h][e] fp16.
// ---------------------------------------------------------------------------
__global__ __launch_bounds__(256) void wtrans_kernel(
    const float* __restrict__ Wq,
    const float* __restrict__ Wk,
    const float* __restrict__ Wv)
{
    __shared__ float t[64][65];
    const int mat = blockIdx.y;
    const int e0  = blockIdx.x * 64;
    const float* W = (mat == 0) ? Wq : (mat == 1) ? Wk : Wv;

    for (int idx = threadIdx.x; idx < 64 * 64; idx += 256) {
        int e = idx >> 6, h = idx & 63;
        t[e][h] = W[(size_t)(e0 + e) * Hn + h];
    }
    __syncthreads();
    for (int idx = threadIdx.x; idx < 64 * 64; idx += 256) {
        int h = idx >> 6, e = idx & 63;
        g_wt[(size_t)(mat * Hn + h) * En + e0 + e] = __float2half_rn(t[e][h]);
    }
}

// ---------------------------------------------------------------------------
// QKV projection via WMMA (m16n16k16, f16 -> f32).
// Q,K stored [t][h]; V stored TRANSPOSED [h][t] via col-major wmma store.
// ---------------------------------------------------------------------------
__global__ __launch_bounds__(256) void qkv_wmma_kernel(
    const float* __restrict__ x)
{
    __shared__ __align__(32) __half xs[64][72];
    __shared__ __align__(32) __half ws[3][64][72];

    const int tid  = threadIdx.x;
    const int warp = tid >> 5;
    const int m0   = blockIdx.x * 64;
    const int rt   = warp & 3;
    const int ctb  = (warp >> 2) * 2;

    wmma::fragment<wmma::accumulator, 16, 16, 16, float> acc[3][2];
#pragma unroll
    for (int m = 0; m < 3; m++)
#pragma unroll
        for (int i = 0; i < 2; i++) wmma::fill_fragment(acc[m][i], 0.f);

    for (int e0 = 0; e0 < En; e0 += 64) {
        __syncthreads();
        for (int idx = tid; idx < 64 * 16; idx += 256) {
            int r = idx >> 4, e4 = (idx & 15) * 4;
            float4 v = *(const float4*)&x[(size_t)(m0 + r) * En + e0 + e4];
            *(__half2*)&xs[r][e4]     = __floats2half2_rn(v.x, v.y);
            *(__half2*)&xs[r][e4 + 2] = __floats2half2_rn(v.z, v.w);
        }
        for (int idx = tid; idx < 3 * 64 * 8; idx += 256) {
            int mat = idx >> 9;
            int rem = idx & 511;
            int h   = rem >> 3;
            int c8  = (rem & 7) * 8;
            *(uint4*)&ws[mat][h][c8] =
                *(const uint4*)&g_wt[(size_t)(mat * Hn + h) * En + e0 + c8];
        }
        __syncthreads();

#pragma unroll
        for (int ks = 0; ks < 4; ks++) {
            wmma::fragment<wmma::matrix_a, 16, 16, 16, __half, wmma::row_major> a;
            wmma::load_matrix_sync(a, &xs[rt * 16][ks * 16], 72);
#pragma unroll
            for (int mat = 0; mat < 3; mat++) {
#pragma unroll
                for (int i = 0; i < 2; i++) {
                    wmma::fragment<wmma::matrix_b, 16, 16, 16, __half, wmma::col_major> b;
                    wmma::load_matrix_sync(b, &ws[mat][(ctb + i) * 16][ks * 16], 72);
                    wmma::mma_sync(acc[mat][i], a, b, acc[mat][i]);
                }
            }
        }
    }

    const int bb = m0 >> 11;            // batch
    const int t0 = (m0 & 2047) + rt * 16;
#pragma unroll
    for (int i = 0; i < 2; i++) {
        wmma::store_matrix_sync(&g_q[(size_t)(m0 + rt * 16) * Hn + (ctb + i) * 16],
                                acc[0][i], Hn, wmma::mem_row_major);
        wmma::store_matrix_sync(&g_k[(size_t)(m0 + rt * 16) * Hn + (ctb + i) * 16],
                                acc[1][i], Hn, wmma::mem_row_major);
        // V transposed: element (row t, col h) -> g_vt[b][h][t]
        wmma::store_matrix_sync(&g_vt[(size_t)bb * Hn * Tn
                                      + (size_t)((ctb + i) * 16) * Tn + t0],
                                acc[2][i], Tn, wmma::mem_col_major);
    }
}

// ---------------------------------------------------------------------------
// Flash attention, all-register FA2 style on mma.sync.m16n8k16.
// grid (T/64 reversed, B), 128 threads = 4 warps; warp owns 16 query rows.
// S, P, O in registers; K tile and V^T tile in smem (pitch 72 halfs,
// conflict-free: bank = 4*key + e_word, all 32 distinct).
// Documented m16n8k16 layouts: C rows = lane>>2 (+8), cols = n*8+(lane&3)*2.
// ---------------------------------------------------------------------------
__device__ __forceinline__ void mma16816(
    float& c0, float& c1, float& c2, float& c3,
    unsigned a0, unsigned a1, unsigned a2, unsigned a3,
    unsigned b0, unsigned b1)
{
    asm volatile(
        "mma.sync.aligned.m16n8k16.row.col.f32.f16.f16.f32 "
        "{%0,%1,%2,%3}, {%4,%5,%6,%7}, {%8,%9}, {%0,%1,%2,%3};\n"
        : "+f"(c0), "+f"(c1), "+f"(c2), "+f"(c3)
        : "r"(a0), "r"(a1), "r"(a2), "r"(a3), "r"(b0), "r"(b1));
}

__device__ __forceinline__ unsigned packh2(float a, float b)
{
    __half2 h = __floats2half2_rn(a, b);
    return *(unsigned*)&h;
}

__global__ __launch_bounds__(128) void attn_kernel(float* __restrict__ out)
{
    __shared__ __align__(32) __half KH[64][72];   // [key][e]
    __shared__ __align__(32) __half VT[64][72];   // [h][key]

    const int b    = blockIdx.y;
    const int i0   = (gridDim.x - 1 - blockIdx.x) * 64;  // heavy first
    const int tid  = threadIdx.x;
    const int warp = tid >> 5;
    const int lane = tid & 31;
    const int g    = lane >> 2;       // fragment row (groupID)
    const int qd   = lane & 3;        // thread in quad
    const int rw   = warp * 16;       // warp's row base in tile

    const float* q  = g_q  + (size_t)b * Tn * Hn;
    const float* k  = g_k  + (size_t)b * Tn * Hn;
    const float* vt = g_vt + (size_t)b * Hn * Tn;

    // ---- Q A-fragments (held for whole kernel) ----
    unsigned aq[4][4];
#pragma unroll
    for (int kc = 0; kc < 4; kc++) {
        const int row0 = i0 + rw + g, row1 = row0 + 8, col = kc * 16 + qd * 2;
        float2 x0 = *(const float2*)&q[(size_t)row0 * Hn + col];
        float2 x1 = *(const float2*)&q[(size_t)row1 * Hn + col];
        float2 x2 = *(const float2*)&q[(size_t)row0 * Hn + col + 8];
        float2 x3 = *(const float2*)&q[(size_t)row1 * Hn + col + 8];
        aq[kc][0] = packh2(x0.x, x0.y);
        aq[kc][1] = packh2(x1.x, x1.y);
        aq[kc][2] = packh2(x2.x, x2.y);
        aq[kc][3] = packh2(x3.x, x3.y);
    }

    float m_[2] = { -1e30f, -1e30f };
    float l_[2] = { 0.f, 0.f };
    float o[8][4];
#pragma unroll
    for (int nt = 0; nt < 8; nt++)
#pragma unroll
        for (int u = 0; u < 4; u++) o[nt][u] = 0.f;

    for (int j0 = 0; j0 <= i0; j0 += 64) {
        const bool diag = (j0 == i0);
        __syncthreads();
        // ---- cooperative loads: KH[key][e], VT[h][key] ----
        for (int idx = tid; idx < 64 * 16; idx += 128) {
            int r = idx >> 4, c4 = (idx & 15) * 4;
            float4 kv = *(const float4*)&k[(size_t)(j0 + r) * Hn + c4];
            *(__half2*)&KH[r][c4]     = __floats2half2_rn(kv.x, kv.y);
            *(__half2*)&KH[r][c4 + 2] = __floats2half2_rn(kv.z, kv.w);
            float4 vv = *(const float4*)&vt[(size_t)r * Tn + j0 + c4];
            *(__half2*)&VT[r][c4]     = __floats2half2_rn(vv.x, vv.y);
            *(__half2*)&VT[r][c4 + 2] = __floats2half2_rn(vv.z, vv.w);
        }
        __syncthreads();

        // ---- S = Q K^T (rows rw..rw+15, cols 0..63) ----
        float s[8][4];
#pragma unroll
        for (int nt = 0; nt < 8; nt++) {
            s[nt][0] = s[nt][1] = s[nt][2] = s[nt][3] = 0.f;
#pragma unroll
            for (int kc = 0; kc < 4; kc++) {
                unsigned b0 = *(const unsigned*)&KH[nt * 8 + g][kc * 16 + qd * 2];
                unsigned b1 = *(const unsigned*)&KH[nt * 8 + g][kc * 16 + qd * 2 + 8];
                mma16816(s[nt][0], s[nt][1], s[nt][2], s[nt][3],
                         aq[kc][0], aq[kc][1], aq[kc][2], aq[kc][3], b0, b1);
            }
        }

        // ---- scale + mask + register online softmax ----
        const int row0 = i0 + rw + g, row1 = row0 + 8;
        float mn0 = m_[0], mn1 = m_[1];
#pragma unroll
        for (int nt = 0; nt < 8; nt++) {
#pragma unroll
            for (int u = 0; u < 2; u++) {
                int colg = j0 + nt * 8 + qd * 2 + u;
                float v0 = s[nt][u] * 0.125f;
                float v1 = s[nt][2 + u] * 0.125f;
                if (diag && colg > row0) v0 = -1e30f;
                if (diag && colg > row1) v1 = -1e30f;
                s[nt][u] = v0; s[nt][2 + u] = v1;
                mn0 = fmaxf(mn0, v0); mn1 = fmaxf(mn1, v1);
            }
        }
        mn0 = fmaxf(mn0, __shfl_xor_sync(0xFFFFFFFFu, mn0, 1));
        mn0 = fmaxf(mn0, __shfl_xor_sync(0xFFFFFFFFu, mn0, 2));
        mn1 = fmaxf(mn1, __shfl_xor_sync(0xFFFFFFFFu, mn1, 1));
        mn1 = fmaxf(mn1, __shfl_xor_sync(0xFFFFFFFFu, mn1, 2));

        float sum0 = 0.f, sum1 = 0.f;
        unsigned ap[4][4];
#pragma unroll
        for (int nt = 0; nt < 8; nt++) {
            float p0 = __expf(s[nt][0] - mn0);
            float p1 = __expf(s[nt][1] - mn0);
            float p2 = __expf(s[nt][2] - mn1);
            float p3 = __expf(s[nt][3] - mn1);
            sum0 += p0 + p1; sum1 += p2 + p3;
            // S cols nt*8+qd*2 == A-frag k (kc=nt>>1, hi-half = nt&1)
            ap[nt >> 1][(nt & 1) ? 2 : 0] = packh2(p0, p1);   // row g
            ap[nt >> 1][(nt & 1) ? 3 : 1] = packh2(p2, p3);   // row g+8
        }
        sum0 += __shfl_xor_sync(0xFFFFFFFFu, sum0, 1);
        sum0 += __shfl_xor_sync(0xFFFFFFFFu, sum0, 2);
        sum1 += __shfl_xor_sync(0xFFFFFFFFu, sum1, 1);
        sum1 += __shfl_xor_sync(0xFFFFFFFFu, sum1, 2);

        const float al0 = __expf(m_[0] - mn0);
        const float al1 = __expf(m_[1] - mn1);
        m_[0] = mn0; m_[1] = mn1;
        l_[0] = l_[0] * al0 + sum0;
        l_[1] = l_[1] * al1 + sum1;

        // ---- O = O*alpha + P V ----
#pragma unroll
        for (int nt = 0; nt < 8; nt++) {
            o[nt][0] *= al0; o[nt][1] *= al0;
            o[nt][2] *= al1; o[nt][3] *= al1;
        }
#pragma unroll
        for (int ht = 0; ht < 8; ht++) {
#pragma unroll
            for (int kc = 0; kc < 4; kc++) {
                unsigned b0 = *(const unsigned*)&VT[ht * 8 + g][kc * 16 + qd * 2];
                unsigned b1 = *(const unsigned*)&VT[ht * 8 + g][kc * 16 + qd * 2 + 8];
                mma16816(o[ht][0], o[ht][1], o[ht][2], o[ht][3],
                         ap[kc][0], ap[kc][1], ap[kc][2], ap[kc][3], b0, b1);
            }
        }
    }

    // ---- epilogue: normalize + write ----
    const float inv0 = 1.f / l_[0];
    const float inv1 = 1.f / l_[1];
    const int row0 = i0 + rw + g, row1 = row0 + 8;
#pragma unroll
    for (int ht = 0; ht < 8; ht++) {
        int col = ht * 8 + qd * 2;
        *(float2*)&out[((size_t)b * Tn + row0) * Hn + col] =
            make_float2(o[ht][0] * inv0, o[ht][1] * inv0);
        *(float2*)&out[((size_t)b * Tn + row1) * Hn + col] =
            make_float2(o[ht][2] * inv1, o[ht][3] * inv1);
    }
}

extern "C" void kernel_launch(void* const* d_in, const int* in_sizes, int n_in,
                              void* d_out, int out_size)
{
    const float* x  = (const float*)d_in[0];
    const float* Wq = (const float*)d_in[1];
    const float* Wk = (const float*)d_in[2];
    const float* Wv = (const float*)d_in[3];
    float* out = (float*)d_out;
    (void)in_sizes; (void)n_in; (void)out_size;

    dim3 wgrid(En / 64, 3);
    wtrans_kernel<<<wgrid, 256>>>(Wq, Wk, Wv);

    qkv_wmma_kernel<<<(Bn * Tn) / 64, 256>>>(x);

    dim3 grid(Tn / 64, Bn);
    attn_kernel<<<grid, 128>>>(out);
}